// round 10
// baseline (speedup 1.0000x reference)
#include <cuda_runtime.h>
#include <cstdint>

// ---------------------------------------------------------------------------
// SSD post-processing:
//   inputs:  loc [32,8732,4] f32, conf [32,8732,21] f32, priors [8732,4] f32
//   output:  [32,21,200,5] f32  rows = [score, x1, y1, x2, y2]
// ---------------------------------------------------------------------------

#define BATCH 32
#define NPRI  8732
#define NPRI4 2183          /* 8732 / 4 exactly */
#define NCLS  21
#define TOPK  200
#define CAP   384           /* candidate capacity (== NTB: 1 thread/candidate) */
#define NW    7             /* ceil(200/32) suppression words */
#define SUPW  8             /* padded row width */
#define NTB   384           /* threads per select block */
#define CITER 6             /* ceil(NPRI4 / NTB) */
#define STHR  50            /* sampled suffix target (~284 est. candidates) */
#define CONF_T 0.01f
#define NMS_T  0.45f
#define NMS_HI 0.45000180f  /* 0.45*(1+4e-6) */
#define NMS_LO 0.44999820f  /* 0.45*(1-4e-6) */
#define BASE16 0x3C00u      /* top16 of float bits; all valid keys above this */

// scratch (module-load allocated, not runtime alloc)
__device__ __align__(16) uint32_t g_keys[BATCH][NCLS-1][NPRI];
__device__ float4 g_boxes[BATCH][NPRI];

// ---------------------------------------------------------------------------
// Kernel A: softmax + decode. One thread per (b, prior). HBM-roofline bound.
// ---------------------------------------------------------------------------
__global__ __launch_bounds__(256) void ssd_decode_softmax(
    const float* __restrict__ loc,
    const float* __restrict__ conf,
    const float* __restrict__ priors)
{
    int t = blockIdx.x * blockDim.x + threadIdx.x;
    if (t >= BATCH * NPRI) return;
    int b = t / NPRI;
    int p = t - b * NPRI;

    const float* cf = conf + (size_t)t * NCLS;
    float v[NCLS];
    float m = -1e30f;
#pragma unroll
    for (int c = 0; c < NCLS; c++) {
        float x = cf[c];
        x = fminf(fmaxf(x, -100.0f), 100.0f);
        v[c] = x;
        m = fmaxf(m, x);
    }
    float s = 0.0f;
#pragma unroll
    for (int c = 0; c < NCLS; c++) { v[c] = expf(v[c] - m); s += v[c]; }

    const float4 lp4 = ((const float4*)loc)[t];
    const float4 pr4 = ((const float4*)priors)[p];
    float p0 = fmaxf(pr4.x, 1e-6f);
    float p1 = fmaxf(pr4.y, 1e-6f);
    float p2 = fmaxf(pr4.z, 1e-6f);
    float p3 = fmaxf(pr4.w, 1e-6f);
    float cx = p0 + lp4.x * 0.1f * p2;
    float cy = p1 + lp4.y * 0.1f * p3;
    float lw = fminf(fmaxf(lp4.z * 0.2f, -4.0f), 4.0f);
    float lh = fminf(fmaxf(lp4.w * 0.2f, -4.0f), 4.0f);
    float w = p2 * expf(lw);
    float h = p3 * expf(lh);
    float x1 = fminf(fmaxf(cx - w / 2.0f, 0.0f), 1.0f);
    float y1 = fminf(fmaxf(cy - h / 2.0f, 0.0f), 1.0f);
    float x2 = fminf(fmaxf(cx + w / 2.0f, 0.0f), 1.0f);
    float y2 = fminf(fmaxf(cy + h / 2.0f, 0.0f), 1.0f);
    g_boxes[b][p] = make_float4(x1, y1, x2, y2);

    bool bvalid = (x2 > x1 + 1e-6f) && (y2 > y1 + 1e-6f);
#pragma unroll
    for (int c = 1; c < NCLS; c++) {
        float sc = v[c] / s;
        uint32_t key = (bvalid && sc > CONF_T) ? __float_as_uint(sc) : 0u;
        g_keys[b][c - 1][p] = key;
    }
}

// ---------------------------------------------------------------------------
// Kernel B: per (image,class): SAMPLED histogram threshold estimate +
// exact-count collect with verify (exact-histogram fallback ~1% of blocks),
// O(n^2) exact rank, split-row IoU masks, warp-parallel sweep + compaction.
// 384 threads, 5 blocks/SM -> single wave for 672 blocks. ~19KB smem.
// ---------------------------------------------------------------------------
__global__ __launch_bounds__(NTB, 5) void ssd_select_nms(float* __restrict__ out)
{
    __shared__ int hist[1024];
    __shared__ int part[256];
    __shared__ unsigned long long spk[CAP];
    __shared__ uint32_t sup[TOPK * SUPW];
    __shared__ float4 sbx[224];        /* padded: IoU reads j up to 223 (masked) */
    __shared__ float ssc[TOPK];
    __shared__ uint32_t salive[8];
    __shared__ int sbase[8];
    __shared__ int sh[8];

    int bc = blockIdx.x;
    int b = bc / NCLS;
    int c = bc - b * NCLS;
    int tid = threadIdx.x;
    int lane = tid & 31;
    float* orow = out + (size_t)bc * (TOPK * 5);

    if (c == 0) {
        for (int i = tid; i < TOPK * 5; i += NTB) orow[i] = 0.0f;
        return;
    }

    const uint32_t* gk = &g_keys[b][c - 1][0];
    const uint4* gk4 = (const uint4*)gk;

    // ---- S0: SAMPLED histogram (384 of 2183 uint4 groups, spread evenly) ----
    for (int i = tid; i < 1024; i += NTB) hist[i] = 0;
    __syncthreads();
    {
        int i = (tid * NPRI4) / NTB;     /* strictly increasing, 384 samples */
        uint4 v = gk4[i];
        if (v.x) atomicAdd(&hist[(v.x >> 16) - BASE16], 1);
        if (v.y) atomicAdd(&hist[(v.y >> 16) - BASE16], 1);
        if (v.z) atomicAdd(&hist[(v.z >> 16) - BASE16], 1);
        if (v.w) atomicAdd(&hist[(v.w >> 16) - BASE16], 1);
    }
    __syncthreads();
    if (tid < 256) {
        int4 h4 = ((const int4*)hist)[tid];
        part[tid] = h4.x + h4.y + h4.z + h4.w;
    }
    __syncthreads();

    // ---- S1: warp 0 picks estimated digit (sampled suffix >= STHR) ----
    if (tid < 32) {
        int s = 0;
#pragma unroll
        for (int q = 0; q < 8; q++) s += part[tid * 8 + q];
        int suf = s;
#pragma unroll
        for (int d = 1; d < 32; d <<= 1) {
            int o = __shfl_down_sync(0xFFFFFFFFu, suf, d);
            if (tid + d < 32) suf += o;
        }
        int sufN = __shfl_down_sync(0xFFFFFFFFu, suf, 1);
        if (tid == 31) sufN = 0;
        if (tid == 0) { sh[0] = -1; sh[6] = 0; }
        __syncwarp();
        if (suf >= STHR && sufN < STHR) { sh[0] = tid; sh[1] = sufN; }
        __syncwarp();
        if (tid == 0 && sh[0] >= 0) {
            int cum = sh[1];
            int d = sh[0] * 32 + 31;
            for (;; d--) { cum += hist[d]; if (cum >= STHR) break; }
            sh[3] = d;
        }
    }
    __syncthreads();

    bool takeAll = (sh[0] < 0);
    uint32_t thrK = takeAll ? (BASE16 << 16)
                            : ((uint32_t)(BASE16 + (uint32_t)sh[3]) << 16);
    for (int i = tid; i < TOPK; i += NTB) ssc[i] = -1.0f;

    // ---- S2: collect keys >= estimated threshold; exact count; bounded write ----
#pragma unroll
    for (int it = 0; it < CITER; it++) {
        int i = tid + it * NTB;
        uint4 v = (i < NPRI4) ? gk4[i] : make_uint4(0u, 0u, 0u, 0u);
        int base4 = i * 4;
#pragma unroll
        for (int comp = 0; comp < 4; comp++) {
            uint32_t k = (comp == 0) ? v.x : (comp == 1) ? v.y : (comp == 2) ? v.z : v.w;
            int take = (k >= thrK);
            uint32_t bm = __ballot_sync(0xFFFFFFFFu, take);
            if (bm) {
                int ldr = __ffs(bm) - 1;
                int pos = 0;
                if (lane == ldr) pos = atomicAdd(&sh[6], __popc(bm));
                pos = __shfl_sync(0xFFFFFFFFu, pos, ldr);
                if (take) {
                    int w = pos + __popc(bm & ((1u << lane) - 1u));
                    if (w < CAP)
                        spk[w] = ((unsigned long long)k << 32)
                               | (uint32_t)~(uint32_t)(base4 + comp);
                }
            }
        }
    }
    __syncthreads();
    int ncand = sh[6];
    bool ok = (ncand <= CAP) && (takeAll || ncand >= TOPK);

    if (!ok) {
        // ================= FALLBACK: exact histogram + select =================
        for (int i = tid; i < 1024; i += NTB) hist[i] = 0;
        __syncthreads();
        for (int i = tid; i < NPRI4; i += NTB) {
            uint4 v = gk4[i];
            if (v.x) atomicAdd(&hist[(v.x >> 16) - BASE16], 1);
            if (v.y) atomicAdd(&hist[(v.y >> 16) - BASE16], 1);
            if (v.z) atomicAdd(&hist[(v.z >> 16) - BASE16], 1);
            if (v.w) atomicAdd(&hist[(v.w >> 16) - BASE16], 1);
        }
        __syncthreads();
        if (tid < 256) {
            int4 h4 = ((const int4*)hist)[tid];
            part[tid] = h4.x + h4.y + h4.z + h4.w;
        }
        __syncthreads();
        if (tid < 32) {
            int s = 0;
#pragma unroll
            for (int q = 0; q < 8; q++) s += part[tid * 8 + q];
            int suf = s;
#pragma unroll
            for (int d = 1; d < 32; d <<= 1) {
                int o = __shfl_down_sync(0xFFFFFFFFu, suf, d);
                if (tid + d < 32) suf += o;
            }
            int sufN = __shfl_down_sync(0xFFFFFFFFu, suf, 1);
            if (tid == 31) sufN = 0;
            if (tid == 0) { sh[0] = -1; sh[6] = 0; }
            __syncwarp();
            if (suf >= TOPK && sufN < TOPK) { sh[0] = tid; sh[1] = sufN; }
            __syncwarp();
            if (tid == 0 && sh[0] >= 0) {
                int cum = sh[1];
                int d = sh[0] * 32 + 31;
                for (;; d--) { cum += hist[d]; if (cum >= TOPK) break; }
                sh[3] = d;
                sh[4] = cum - hist[d];
                sh[5] = hist[d];
            }
        }
        __syncthreads();

        bool rare = (sh[0] >= 0) && (sh[4] + sh[5] > CAP);
        if (!rare) {
            uint32_t t2 = (sh[0] < 0) ? (BASE16 << 16)
                                      : ((uint32_t)(BASE16 + (uint32_t)sh[3]) << 16);
#pragma unroll
            for (int it = 0; it < CITER; it++) {
                int i = tid + it * NTB;
                uint4 v = (i < NPRI4) ? gk4[i] : make_uint4(0u, 0u, 0u, 0u);
                int base4 = i * 4;
#pragma unroll
                for (int comp = 0; comp < 4; comp++) {
                    uint32_t k = (comp == 0) ? v.x : (comp == 1) ? v.y : (comp == 2) ? v.z : v.w;
                    int take = (k >= t2);
                    uint32_t bm = __ballot_sync(0xFFFFFFFFu, take);
                    if (bm) {
                        int ldr = __ffs(bm) - 1;
                        int pos = 0;
                        if (lane == ldr) pos = atomicAdd(&sh[6], __popc(bm));
                        pos = __shfl_sync(0xFFFFFFFFu, pos, ldr);
                        if (take) {
                            int w = pos + __popc(bm & ((1u << lane) - 1u));
                            if (w < CAP)
                                spk[w] = ((unsigned long long)k << 32)
                                       | (uint32_t)~(uint32_t)(base4 + comp);
                        }
                    }
                }
            }
            __syncthreads();
            ncand = sh[6];
        } else {
            // massive ties at the cut digit: refine to exact 32-bit threshold
            uint32_t top16 = BASE16 + (uint32_t)sh[3];
            int cnt_gt = sh[4];
            if (tid < 256) hist[tid] = 0;
            __syncthreads();
            for (int i = tid; i < NPRI; i += NTB) {
                uint32_t k = gk[i];
                if ((k >> 16) == top16) atomicAdd(&hist[(k >> 8) & 0xFF], 1);
            }
            __syncthreads();
            if (tid == 0) {
                int cum = cnt_gt; int d = 255;
                for (;; d--) { cum += hist[d]; if (cum >= TOPK) break; }
                sh[3] = d; sh[4] = cum - hist[d];
            }
            __syncthreads();
            uint32_t pre24 = (top16 << 8) | (uint32_t)sh[3];
            cnt_gt = sh[4];
            if (tid < 256) hist[tid] = 0;
            __syncthreads();
            for (int i = tid; i < NPRI; i += NTB) {
                uint32_t k = gk[i];
                if ((k >> 8) == pre24) atomicAdd(&hist[k & 0xFF], 1);
            }
            __syncthreads();
            if (tid == 0) {
                int cum = cnt_gt; int d = 255;
                for (;; d--) { cum += hist[d]; if (cum >= TOPK) break; }
                sh[3] = d;
                sh[6] = 0;
            }
            __syncthreads();
            uint32_t thr = ((pre24 << 8) | (uint32_t)sh[3]);
            for (int i = tid; i < NPRI; i += NTB) {
                uint32_t k = gk[i];
                if (k > thr) {
                    int p = atomicAdd(&sh[6], 1);
                    if (p < CAP)
                        spk[p] = ((unsigned long long)k << 32) | (uint32_t)~(uint32_t)i;
                }
            }
            __syncthreads();
            if (tid == 0) {   // append ties in ascending index order
                int p = sh[6];
                for (int i = 0; i < NPRI && p < TOPK; i++)
                    if (gk[i] == thr) { spk[p++] = ((unsigned long long)thr << 32) | (uint32_t)~(uint32_t)i; }
                sh[6] = p;
            }
            __syncthreads();
            ncand = sh[6];
        }
        if (ncand > CAP) ncand = CAP;   // safety (rare path bounds writes)
    }

    // ---- P3: exact rank (key desc, index asc) + gather; zero output rows ----
    for (int i = tid; i < TOPK * 5; i += NTB) orow[i] = 0.0f;
    if (tid < ncand) {
        unsigned long long mypk = spk[tid];
        int rank = 0;
#pragma unroll 4
        for (int j = 0; j < ncand; j++) rank += (spk[j] > mypk) ? 1 : 0;
        if (rank < TOPK) {
            uint32_t kk = (uint32_t)(mypk >> 32);
            uint32_t idx = ~(uint32_t)mypk;
            float4 bx = g_boxes[b][idx];
            ssc[rank] = __uint_as_float(kk);
            sbx[rank] = bx;
        }
    }
    __syncthreads();
    int nval = ncand < TOPK ? ncand : TOPK;

    // ---- P4: IoU suppression masks. Row i split: main thread (tid=i) does the
    //      low half of its word span, helper (tid=200+i, i<184) the high half.
    //      Areas recomputed from boxes (saves LDS; same fp32 formula as ref).
    {
        int i = -1, w0 = 0, w1 = 0;
        if (tid < TOPK) {
            i = tid;
            int wl = i >> 5, span = NW - wl;
            int mine = (i < 184) ? ((span + 1) >> 1) : span;
            w0 = wl; w1 = wl + mine;
        } else if (tid - TOPK < 184) {
            i = tid - TOPK;
            int wl = i >> 5, span = NW - wl;
            w0 = wl + ((span + 1) >> 1); w1 = NW;
        }
        if (i >= 0 && i < nval) {
            if (tid < TOPK)
                for (int w = 0; w < (i >> 5); w++) sup[i * SUPW + w] = 0u;
            float4 A = sbx[i];
            float aa = (A.z - A.x) * (A.w - A.y);
            for (int w = w0; w < w1; w++) {
                int j0 = w * 32;
                uint32_t m = 0;
#pragma unroll
                for (int jj = 0; jj < 32; jj++) {
                    int j = j0 + jj;
                    float4 B = sbx[j];
                    float ab = (B.z - B.x) * (B.w - B.y);
                    float xx1 = fmaxf(A.x, B.x);
                    float yy1 = fmaxf(A.y, B.y);
                    float xx2 = fminf(A.z, B.z);
                    float yy2 = fminf(A.w, B.w);
                    float iw = fmaxf(xx2 - xx1, 0.0f);
                    float ih = fmaxf(yy2 - yy1, 0.0f);
                    float inter = iw * ih;
                    float uni = aa + ab - inter;
                    uint32_t bit = 0;
                    if (inter > uni * NMS_HI) bit = 1u << jj;
                    else if (inter > uni * NMS_LO) {
                        if (inter / fmaxf(uni, 1e-12f) > NMS_T) bit = 1u << jj;  // exact ref
                    }
                    m |= bit;
                }
                uint32_t um = (nval >= j0 + 32) ? 0xFFFFFFFFu
                             : ((nval > j0) ? ((1u << (nval - j0)) - 1u) : 0u);
                if (w == (i >> 5))
                    um = (i - j0 < 31) ? (um & (0xFFFFFFFFu << (i - j0 + 1))) : 0u;
                sup[i * SUPW + w] = m & um;
            }
        }
    }
    __syncthreads();

    // ---- P5: warp-parallel NMS sweep (warp 0) + popc compaction bases ----
    if (tid < 32) {
        uint32_t alive_w = 0xFFFFFFFFu;
        int nchunks = (nval + 31) >> 5;
        for (int g = 0; g < nchunks; g++) {
            int rem = nval - g * 32;
            uint32_t vm = (rem >= 32) ? 0xFFFFFFFFu : ((1u << rem) - 1u);
            uint32_t ag = __shfl_sync(0xFFFFFFFFu, alive_w, g) & vm;
            // intra-chunk serial resolve via shuffles (register chain, no LDS)
            uint32_t selfm = (lane < rem) ? sup[(g * 32 + lane) * SUPW + g] : 0u;
#pragma unroll
            for (int bit = 0; bit < 32; bit++) {
                uint32_t sm = __shfl_sync(0xFFFFFFFFu, selfm, bit);
                if ((ag >> bit) & 1u) ag &= ~sm;
            }
            if (lane == g) alive_w = ag;
            // apply chunk g's alive rows to later words (independent LDS, pipelined)
            uint32_t acc = 0;
            int waddr = (lane < NW) ? lane : NW - 1;
#pragma unroll
            for (int bit = 0; bit < 32; bit++) {
                uint32_t s = (bit < rem) ? sup[(g * 32 + bit) * SUPW + waddr] : 0u;
                if ((ag >> bit) & 1u) acc |= s;
            }
            if (lane > g && lane < NW) alive_w &= ~acc;
        }
        uint32_t aw = (lane < NW && lane < nchunks) ? alive_w : 0u;
        if (lane == nchunks - 1) {
            int rem = nval - lane * 32;
            if (rem < 32) aw &= ((1u << (rem > 0 ? rem : 0)) - 1u);
        }
        int pc = __popc(aw);
        int pre = pc;
#pragma unroll
        for (int d = 1; d < 32; d <<= 1) {
            int o = __shfl_up_sync(0xFFFFFFFFu, pre, d);
            if (lane >= d) pre += o;
        }
        if (lane < NW) { salive[lane] = aw; sbase[lane] = pre - pc; }
    }
    __syncthreads();

    // ---- P6: write kept rows compacted to front ----
    for (int i = tid; i < nval; i += NTB) {
        int w = i >> 5, bit = i & 31;
        uint32_t aw = salive[w];
        if ((aw >> bit) & 1u) {
            int q = sbase[w] + __popc(aw & ((1u << bit) - 1u));
            float* r = orow + q * 5;
            float4 bx = sbx[i];
            r[0] = ssc[i];
            r[1] = bx.x;
            r[2] = bx.y;
            r[3] = bx.z;
            r[4] = bx.w;
        }
    }
}

// ---------------------------------------------------------------------------
extern "C" void kernel_launch(void* const* d_in, const int* in_sizes, int n_in,
                              void* d_out, int out_size)
{
    const float* loc    = (const float*)d_in[0];
    const float* conf   = (const float*)d_in[1];
    const float* priors = (const float*)d_in[2];
    float* out = (float*)d_out;

    ssd_decode_softmax<<<(BATCH * NPRI + 255) / 256, 256>>>(loc, conf, priors);
    ssd_select_nms<<<BATCH * NCLS, NTB>>>(out);
}

// round 11
// speedup vs baseline: 1.1835x; 1.1835x over previous
#include <cuda_runtime.h>
#include <cstdint>

// ---------------------------------------------------------------------------
// SSD post-processing:
//   inputs:  loc [32,8732,4] f32, conf [32,8732,21] f32, priors [8732,4] f32
//   output:  [32,21,200,5] f32  rows = [score, x1, y1, x2, y2]
// ---------------------------------------------------------------------------

#define BATCH 32
#define NPRI  8732
#define NPRI4 2183          /* 8732 / 4 exactly */
#define NCLS  21
#define TOPK  200
#define CAP   256           /* candidate capacity (common path) */
#define NW    7             /* ceil(200/32) suppression words */
#define SUPW  8             /* padded row width */
#define NTB   384           /* threads per select block */
#define CITER 6             /* ceil(NPRI4 / NTB) */
#define CONF_T 0.01f
#define NMS_T  0.45f
#define NMS_HI 0.45000180f  /* 0.45*(1+4e-6) */
#define NMS_LO 0.44999820f  /* 0.45*(1-4e-6) */
#define BASE16 0x3C00u      /* top16 of float bits; all valid keys above this */

// scratch (module-load allocated, not runtime alloc)
__device__ __align__(16) uint32_t g_keys[BATCH][NCLS-1][NPRI];
__device__ float4 g_boxes[BATCH][NPRI];

// ---------------------------------------------------------------------------
// Kernel A: softmax + decode. One thread per (b, prior). HBM-roofline bound.
// ---------------------------------------------------------------------------
__global__ __launch_bounds__(256) void ssd_decode_softmax(
    const float* __restrict__ loc,
    const float* __restrict__ conf,
    const float* __restrict__ priors)
{
    int t = blockIdx.x * blockDim.x + threadIdx.x;
    if (t >= BATCH * NPRI) return;
    int b = t / NPRI;
    int p = t - b * NPRI;

    const float* cf = conf + (size_t)t * NCLS;
    float v[NCLS];
    float m = -1e30f;
#pragma unroll
    for (int c = 0; c < NCLS; c++) {
        float x = cf[c];
        x = fminf(fmaxf(x, -100.0f), 100.0f);
        v[c] = x;
        m = fmaxf(m, x);
    }
    float s = 0.0f;
#pragma unroll
    for (int c = 0; c < NCLS; c++) { v[c] = expf(v[c] - m); s += v[c]; }

    const float4 lp4 = ((const float4*)loc)[t];
    const float4 pr4 = ((const float4*)priors)[p];
    float p0 = fmaxf(pr4.x, 1e-6f);
    float p1 = fmaxf(pr4.y, 1e-6f);
    float p2 = fmaxf(pr4.z, 1e-6f);
    float p3 = fmaxf(pr4.w, 1e-6f);
    float cx = p0 + lp4.x * 0.1f * p2;
    float cy = p1 + lp4.y * 0.1f * p3;
    float lw = fminf(fmaxf(lp4.z * 0.2f, -4.0f), 4.0f);
    float lh = fminf(fmaxf(lp4.w * 0.2f, -4.0f), 4.0f);
    float w = p2 * expf(lw);
    float h = p3 * expf(lh);
    float x1 = fminf(fmaxf(cx - w / 2.0f, 0.0f), 1.0f);
    float y1 = fminf(fmaxf(cy - h / 2.0f, 0.0f), 1.0f);
    float x2 = fminf(fmaxf(cx + w / 2.0f, 0.0f), 1.0f);
    float y2 = fminf(fmaxf(cy + h / 2.0f, 0.0f), 1.0f);
    g_boxes[b][p] = make_float4(x1, y1, x2, y2);

    bool bvalid = (x2 > x1 + 1e-6f) && (y2 > y1 + 1e-6f);
#pragma unroll
    for (int c = 1; c < NCLS; c++) {
        float sc = v[c] / s;
        uint32_t key = (bvalid && sc > CONF_T) ? __float_as_uint(sc) : 0u;
        g_keys[b][c - 1][p] = key;
    }
}

// ---------------------------------------------------------------------------
// Kernel B: per (image,class): smem histogram select (double-buffered scan),
// warp-aggregated collect (ONE atomic per warp-iteration), O(n^2) exact rank,
// split-row IoU masks, warp-parallel sweep + compaction.
// 384 threads, 5 blocks/SM -> single wave for 672 blocks. ~19KB smem.
// ---------------------------------------------------------------------------
__global__ __launch_bounds__(NTB, 5) void ssd_select_nms(float* __restrict__ out)
{
    __shared__ int hist[1024];
    __shared__ int part[256];
    __shared__ unsigned long long spk[CAP];
    __shared__ uint32_t sup[TOPK * SUPW];
    __shared__ float4 sbx[224];        /* padded: IoU reads j up to 223 (masked) */
    __shared__ float sar[224], ssc[TOPK];
    __shared__ uint32_t salive[8];
    __shared__ int sbase[8];
    __shared__ int sh[8];

    int bc = blockIdx.x;
    int b = bc / NCLS;
    int c = bc - b * NCLS;
    int tid = threadIdx.x;
    int lane = tid & 31;
    float* orow = out + (size_t)bc * (TOPK * 5);

    if (c == 0) {
        for (int i = tid; i < TOPK * 5; i += NTB) orow[i] = 0.0f;
        return;
    }

    const uint32_t* gk = &g_keys[b][c - 1][0];
    const uint4* gk4 = (const uint4*)gk;
    const uint4 z4 = make_uint4(0u, 0u, 0u, 0u);

    // ---- P0: 16-bit digit histogram, double-buffered scan ----
    for (int i = tid; i < 1024; i += NTB) hist[i] = 0;
    __syncthreads();
    {
        uint4 vcur = (tid < NPRI4) ? gk4[tid] : z4;
#pragma unroll
        for (int it = 0; it < CITER; it++) {
            int inext = tid + (it + 1) * NTB;
            uint4 vnext = (it + 1 < CITER && inext < NPRI4) ? gk4[inext] : z4;
            if (vcur.x) atomicAdd(&hist[(vcur.x >> 16) - BASE16], 1);
            if (vcur.y) atomicAdd(&hist[(vcur.y >> 16) - BASE16], 1);
            if (vcur.z) atomicAdd(&hist[(vcur.z >> 16) - BASE16], 1);
            if (vcur.w) atomicAdd(&hist[(vcur.w >> 16) - BASE16], 1);
            vcur = vnext;
        }
    }
    __syncthreads();
    if (tid < 256) {
        int4 h4 = ((const int4*)hist)[tid];
        part[tid] = h4.x + h4.y + h4.z + h4.w;
    }
    __syncthreads();

    // ---- P1: warp 0 locates the 200th-largest digit via suffix scan ----
    if (tid < 32) {
        int s = 0;
#pragma unroll
        for (int q = 0; q < 8; q++) s += part[tid * 8 + q];
        int suf = s;
#pragma unroll
        for (int d = 1; d < 32; d <<= 1) {
            int o = __shfl_down_sync(0xFFFFFFFFu, suf, d);
            if (tid + d < 32) suf += o;
        }
        int sufN = __shfl_down_sync(0xFFFFFFFFu, suf, 1);
        if (tid == 31) sufN = 0;
        if (tid == 0) { sh[0] = -1; sh[6] = 0; }
        __syncwarp();
        if (suf >= TOPK && sufN < TOPK) { sh[0] = tid; sh[1] = sufN; }
        __syncwarp();
        if (tid == 0 && sh[0] >= 0) {
            int cum = sh[1];
            int d = sh[0] * 32 + 31;
            for (;; d--) { cum += hist[d]; if (cum >= TOPK) break; }
            sh[3] = d;                // digit of 200th value
            sh[4] = cum - hist[d];    // count with digit > d
            sh[5] = hist[d];
        }
    }
    __syncthreads();

    int ncand;
    bool rare = (sh[0] >= 0) && (sh[4] + sh[5] > CAP);
    if (!rare) {
        // ---- P2 common: collect keys >= digit floor; ONE atomic per warp-iter ----
        uint32_t thrK = (sh[0] < 0) ? (BASE16 << 16)
                                    : ((uint32_t)(BASE16 + (uint32_t)sh[3]) << 16);
        for (int i = tid; i < TOPK; i += NTB) ssc[i] = -1.0f;
        {
            uint4 vcur = (tid < NPRI4) ? gk4[tid] : z4;
#pragma unroll
            for (int it = 0; it < CITER; it++) {
                int inext = tid + (it + 1) * NTB;
                uint4 vnext = (it + 1 < CITER && inext < NPRI4) ? gk4[inext] : z4;
                int base4 = (tid + it * NTB) * 4;

                uint32_t bm0 = __ballot_sync(0xFFFFFFFFu, vcur.x >= thrK);
                uint32_t bm1 = __ballot_sync(0xFFFFFFFFu, vcur.y >= thrK);
                uint32_t bm2 = __ballot_sync(0xFFFFFFFFu, vcur.z >= thrK);
                uint32_t bm3 = __ballot_sync(0xFFFFFFFFu, vcur.w >= thrK);
                int c0 = __popc(bm0), c1 = __popc(bm1), c2 = __popc(bm2);
                int tot = c0 + c1 + c2 + __popc(bm3);
                if (tot) {
                    int base = 0;
                    if (lane == 0) base = atomicAdd(&sh[6], tot);
                    base = __shfl_sync(0xFFFFFFFFu, base, 0);
                    uint32_t below = (1u << lane) - 1u;
                    if (vcur.x >= thrK)
                        spk[base + __popc(bm0 & below)] =
                            ((unsigned long long)vcur.x << 32) | (uint32_t)~(uint32_t)(base4 + 0);
                    if (vcur.y >= thrK)
                        spk[base + c0 + __popc(bm1 & below)] =
                            ((unsigned long long)vcur.y << 32) | (uint32_t)~(uint32_t)(base4 + 1);
                    if (vcur.z >= thrK)
                        spk[base + c0 + c1 + __popc(bm2 & below)] =
                            ((unsigned long long)vcur.z << 32) | (uint32_t)~(uint32_t)(base4 + 2);
                    if (vcur.w >= thrK)
                        spk[base + c0 + c1 + c2 + __popc(bm3 & below)] =
                            ((unsigned long long)vcur.w << 32) | (uint32_t)~(uint32_t)(base4 + 3);
                }
                vcur = vnext;
            }
        }
        __syncthreads();
        ncand = sh[6];
    } else {
        // ---- P2 rare (massive ties at cut digit): exact 32-bit refine ----
        for (int i = tid; i < TOPK; i += NTB) ssc[i] = -1.0f;
        uint32_t top16 = BASE16 + (uint32_t)sh[3];
        int cnt_gt = sh[4];
        if (tid < 256) hist[tid] = 0;
        __syncthreads();
        for (int i = tid; i < NPRI; i += NTB) {
            uint32_t k = gk[i];
            if ((k >> 16) == top16) atomicAdd(&hist[(k >> 8) & 0xFF], 1);
        }
        __syncthreads();
        if (tid == 0) {
            int cum = cnt_gt; int d = 255;
            for (;; d--) { cum += hist[d]; if (cum >= TOPK) break; }
            sh[3] = d; sh[4] = cum - hist[d];
        }
        __syncthreads();
        uint32_t pre24 = (top16 << 8) | (uint32_t)sh[3];
        cnt_gt = sh[4];
        if (tid < 256) hist[tid] = 0;
        __syncthreads();
        for (int i = tid; i < NPRI; i += NTB) {
            uint32_t k = gk[i];
            if ((k >> 8) == pre24) atomicAdd(&hist[k & 0xFF], 1);
        }
        __syncthreads();
        if (tid == 0) {
            int cum = cnt_gt; int d = 255;
            for (;; d--) { cum += hist[d]; if (cum >= TOPK) break; }
            sh[3] = d;
        }
        __syncthreads();
        uint32_t thr = (pre24 << 8) | (uint32_t)sh[3];
        for (int i = tid; i < NPRI; i += NTB) {
            uint32_t k = gk[i];
            if (k > thr) { int p = atomicAdd(&sh[6], 1); spk[p] = ((unsigned long long)k << 32) | (uint32_t)~(uint32_t)i; }
        }
        __syncthreads();
        if (tid == 0) {   // append ties in ascending index order
            int p = sh[6];
            for (int i = 0; i < NPRI && p < TOPK; i++)
                if (gk[i] == thr) { spk[p++] = ((unsigned long long)thr << 32) | (uint32_t)~(uint32_t)i; }
            sh[6] = p;
        }
        __syncthreads();
        ncand = sh[6];
    }

    // ---- P3: exact rank (key desc, index asc) + gather; idle threads zero out ----
    if (tid < ncand) {
        unsigned long long mypk = spk[tid];
        int rank = 0;
#pragma unroll 4
        for (int j = 0; j < ncand; j++) rank += (spk[j] > mypk) ? 1 : 0;
        if (rank < TOPK) {
            uint32_t kk = (uint32_t)(mypk >> 32);
            uint32_t idx = ~(uint32_t)mypk;
            float4 bx = g_boxes[b][idx];
            ssc[rank] = __uint_as_float(kk);
            sbx[rank] = bx;
            sar[rank] = (bx.z - bx.x) * (bx.w - bx.y);
        }
    } else if (tid >= 256) {
        for (int i = tid - 256; i < TOPK * 5; i += NTB - 256) orow[i] = 0.0f;
    }
    __syncthreads();
    int nval = ncand < TOPK ? ncand : TOPK;

    // ---- P4: IoU suppression masks. Row i split: main thread (tid=i) does the
    //      low half of its word span, helper (tid=200+i, i<184) the high half.
    {
        int i = -1, w0 = 0, w1 = 0;
        if (tid < TOPK) {
            i = tid;
            int wl = i >> 5, span = NW - wl;
            int mine = (i < 184) ? ((span + 1) >> 1) : span;
            w0 = wl; w1 = wl + mine;
        } else if (tid - TOPK < 184) {
            i = tid - TOPK;
            int wl = i >> 5, span = NW - wl;
            w0 = wl + ((span + 1) >> 1); w1 = NW;
        }
        if (i >= 0 && i < nval) {
            if (tid < TOPK)
                for (int w = 0; w < (i >> 5); w++) sup[i * SUPW + w] = 0u;
            float4 A = sbx[i];
            float aa = sar[i];
            for (int w = w0; w < w1; w++) {
                int j0 = w * 32;
                uint32_t m = 0;
#pragma unroll
                for (int jj = 0; jj < 32; jj++) {
                    int j = j0 + jj;
                    float4 B = sbx[j];
                    float xx1 = fmaxf(A.x, B.x);
                    float yy1 = fmaxf(A.y, B.y);
                    float xx2 = fminf(A.z, B.z);
                    float yy2 = fminf(A.w, B.w);
                    float iw = fmaxf(xx2 - xx1, 0.0f);
                    float ih = fmaxf(yy2 - yy1, 0.0f);
                    float inter = iw * ih;
                    float uni = aa + sar[j] - inter;
                    uint32_t bit = 0;
                    if (inter > uni * NMS_HI) bit = 1u << jj;
                    else if (inter > uni * NMS_LO) {
                        if (inter / fmaxf(uni, 1e-12f) > NMS_T) bit = 1u << jj;  // exact ref
                    }
                    m |= bit;
                }
                uint32_t um = (nval >= j0 + 32) ? 0xFFFFFFFFu
                             : ((nval > j0) ? ((1u << (nval - j0)) - 1u) : 0u);
                if (w == (i >> 5))
                    um = (i - j0 < 31) ? (um & (0xFFFFFFFFu << (i - j0 + 1))) : 0u;
                sup[i * SUPW + w] = m & um;
            }
        }
    }
    __syncthreads();

    // ---- P5: warp-parallel NMS sweep (warp 0) + popc compaction bases ----
    if (tid < 32) {
        uint32_t alive_w = 0xFFFFFFFFu;
        int nchunks = (nval + 31) >> 5;
        for (int g = 0; g < nchunks; g++) {
            int rem = nval - g * 32;
            uint32_t vm = (rem >= 32) ? 0xFFFFFFFFu : ((1u << rem) - 1u);
            uint32_t ag = __shfl_sync(0xFFFFFFFFu, alive_w, g) & vm;
            // intra-chunk serial resolve via shuffles (register chain, no LDS)
            uint32_t selfm = (lane < rem) ? sup[(g * 32 + lane) * SUPW + g] : 0u;
#pragma unroll
            for (int bit = 0; bit < 32; bit++) {
                uint32_t sm = __shfl_sync(0xFFFFFFFFu, selfm, bit);
                if ((ag >> bit) & 1u) ag &= ~sm;
            }
            if (lane == g) alive_w = ag;
            // apply chunk g's alive rows to later words (independent LDS, pipelined)
            uint32_t acc = 0;
            int waddr = (lane < NW) ? lane : NW - 1;
#pragma unroll
            for (int bit = 0; bit < 32; bit++) {
                uint32_t s = (bit < rem) ? sup[(g * 32 + bit) * SUPW + waddr] : 0u;
                if ((ag >> bit) & 1u) acc |= s;
            }
            if (lane > g && lane < NW) alive_w &= ~acc;
        }
        uint32_t aw = (lane < NW && lane < nchunks) ? alive_w : 0u;
        if (lane == nchunks - 1) {
            int rem = nval - lane * 32;
            if (rem < 32) aw &= ((1u << (rem > 0 ? rem : 0)) - 1u);
        }
        int pc = __popc(aw);
        int pre = pc;
#pragma unroll
        for (int d = 1; d < 32; d <<= 1) {
            int o = __shfl_up_sync(0xFFFFFFFFu, pre, d);
            if (lane >= d) pre += o;
        }
        if (lane < NW) { salive[lane] = aw; sbase[lane] = pre - pc; }
    }
    __syncthreads();

    // ---- P6: write kept rows compacted to front ----
    for (int i = tid; i < nval; i += NTB) {
        int w = i >> 5, bit = i & 31;
        uint32_t aw = salive[w];
        if ((aw >> bit) & 1u) {
            int q = sbase[w] + __popc(aw & ((1u << bit) - 1u));
            float* r = orow + q * 5;
            float4 bx = sbx[i];
            r[0] = ssc[i];
            r[1] = bx.x;
            r[2] = bx.y;
            r[3] = bx.z;
            r[4] = bx.w;
        }
    }
}

// ---------------------------------------------------------------------------
extern "C" void kernel_launch(void* const* d_in, const int* in_sizes, int n_in,
                              void* d_out, int out_size)
{
    const float* loc    = (const float*)d_in[0];
    const float* conf   = (const float*)d_in[1];
    const float* priors = (const float*)d_in[2];
    float* out = (float*)d_out;

    ssd_decode_softmax<<<(BATCH * NPRI + 255) / 256, 256>>>(loc, conf, priors);
    ssd_select_nms<<<BATCH * NCLS, NTB>>>(out);
}

// round 12
// speedup vs baseline: 1.1842x; 1.0006x over previous
#include <cuda_runtime.h>
#include <cstdint>

// ---------------------------------------------------------------------------
// SSD post-processing:
//   inputs:  loc [32,8732,4] f32, conf [32,8732,21] f32, priors [8732,4] f32
//   output:  [32,21,200,5] f32  rows = [score, x1, y1, x2, y2]
// ---------------------------------------------------------------------------

#define BATCH 32
#define NPRI  8732
#define NPRI4 2183          /* 8732 / 4 exactly */
#define NCLS  21
#define TOPK  200
#define CAP   256           /* candidate capacity (common path) == sort width */
#define NSORT 256
#define NW    7             /* ceil(200/32) suppression words */
#define SUPW  8             /* padded row width */
#define NTB   384           /* threads per select block */
#define CITER 6             /* ceil(NPRI4 / NTB) */
#define CONF_T 0.01f
#define NMS_T  0.45f
#define NMS_HI 0.45000180f  /* 0.45*(1+4e-6) */
#define NMS_LO 0.44999820f  /* 0.45*(1-4e-6) */
#define BASE16 0x3C00u      /* top16 of float bits; all valid keys above this */

// scratch (module-load allocated, not runtime alloc)
__device__ __align__(16) uint32_t g_keys[BATCH][NCLS-1][NPRI];
__device__ float4 g_boxes[BATCH][NPRI];

// ---------------------------------------------------------------------------
// Kernel A: softmax + decode. One thread per (b, prior). HBM-roofline bound.
// ---------------------------------------------------------------------------
__global__ __launch_bounds__(256) void ssd_decode_softmax(
    const float* __restrict__ loc,
    const float* __restrict__ conf,
    const float* __restrict__ priors)
{
    int t = blockIdx.x * blockDim.x + threadIdx.x;
    if (t >= BATCH * NPRI) return;
    int b = t / NPRI;
    int p = t - b * NPRI;

    const float* cf = conf + (size_t)t * NCLS;
    float v[NCLS];
    float m = -1e30f;
#pragma unroll
    for (int c = 0; c < NCLS; c++) {
        float x = cf[c];
        x = fminf(fmaxf(x, -100.0f), 100.0f);
        v[c] = x;
        m = fmaxf(m, x);
    }
    float s = 0.0f;
#pragma unroll
    for (int c = 0; c < NCLS; c++) { v[c] = expf(v[c] - m); s += v[c]; }

    const float4 lp4 = ((const float4*)loc)[t];
    const float4 pr4 = ((const float4*)priors)[p];
    float p0 = fmaxf(pr4.x, 1e-6f);
    float p1 = fmaxf(pr4.y, 1e-6f);
    float p2 = fmaxf(pr4.z, 1e-6f);
    float p3 = fmaxf(pr4.w, 1e-6f);
    float cx = p0 + lp4.x * 0.1f * p2;
    float cy = p1 + lp4.y * 0.1f * p3;
    float lw = fminf(fmaxf(lp4.z * 0.2f, -4.0f), 4.0f);
    float lh = fminf(fmaxf(lp4.w * 0.2f, -4.0f), 4.0f);
    float w = p2 * expf(lw);
    float h = p3 * expf(lh);
    float x1 = fminf(fmaxf(cx - w / 2.0f, 0.0f), 1.0f);
    float y1 = fminf(fmaxf(cy - h / 2.0f, 0.0f), 1.0f);
    float x2 = fminf(fmaxf(cx + w / 2.0f, 0.0f), 1.0f);
    float y2 = fminf(fmaxf(cy + h / 2.0f, 0.0f), 1.0f);
    g_boxes[b][p] = make_float4(x1, y1, x2, y2);

    bool bvalid = (x2 > x1 + 1e-6f) && (y2 > y1 + 1e-6f);
#pragma unroll
    for (int c = 1; c < NCLS; c++) {
        float sc = v[c] / s;
        uint32_t key = (bvalid && sc > CONF_T) ? __float_as_uint(sc) : 0u;
        g_keys[b][c - 1][p] = key;
    }
}

// ---------------------------------------------------------------------------
// Kernel B: per (image,class): smem histogram select (double-buffered scan),
// warp-aggregated collect (one atomic per warp-iteration), 256-wide bitonic
// sort (exact order: key desc, index asc), split-row IoU masks, warp-parallel
// sweep + compaction. 384 threads, 5 blocks/SM -> single wave for 672 blocks.
// ---------------------------------------------------------------------------
__global__ __launch_bounds__(NTB, 5) void ssd_select_nms(float* __restrict__ out)
{
    __shared__ int hist[1024];
    __shared__ int part[256];
    __shared__ unsigned long long spk[NSORT];
    __shared__ uint32_t sup[TOPK * SUPW];
    __shared__ float4 sbx[224];        /* padded: IoU reads j up to 223 (masked) */
    __shared__ float sar[224], ssc[TOPK];
    __shared__ uint32_t salive[8];
    __shared__ int sbase[8];
    __shared__ int sh[8];

    int bc = blockIdx.x;
    int b = bc / NCLS;
    int c = bc - b * NCLS;
    int tid = threadIdx.x;
    int lane = tid & 31;
    float* orow = out + (size_t)bc * (TOPK * 5);

    if (c == 0) {
        for (int i = tid; i < TOPK * 5; i += NTB) orow[i] = 0.0f;
        return;
    }

    const uint32_t* gk = &g_keys[b][c - 1][0];
    const uint4* gk4 = (const uint4*)gk;
    const uint4 z4 = make_uint4(0u, 0u, 0u, 0u);

    // ---- P0: 16-bit digit histogram, double-buffered scan ----
    for (int i = tid; i < 1024; i += NTB) hist[i] = 0;
    __syncthreads();
    {
        uint4 vcur = (tid < NPRI4) ? gk4[tid] : z4;
#pragma unroll
        for (int it = 0; it < CITER; it++) {
            int inext = tid + (it + 1) * NTB;
            uint4 vnext = (it + 1 < CITER && inext < NPRI4) ? gk4[inext] : z4;
            if (vcur.x) atomicAdd(&hist[(vcur.x >> 16) - BASE16], 1);
            if (vcur.y) atomicAdd(&hist[(vcur.y >> 16) - BASE16], 1);
            if (vcur.z) atomicAdd(&hist[(vcur.z >> 16) - BASE16], 1);
            if (vcur.w) atomicAdd(&hist[(vcur.w >> 16) - BASE16], 1);
            vcur = vnext;
        }
    }
    __syncthreads();
    if (tid < 256) {
        int4 h4 = ((const int4*)hist)[tid];
        part[tid] = h4.x + h4.y + h4.z + h4.w;
    }
    __syncthreads();

    // ---- P1: warp 0 locates the 200th-largest digit via suffix scan ----
    if (tid < 32) {
        int s = 0;
#pragma unroll
        for (int q = 0; q < 8; q++) s += part[tid * 8 + q];
        int suf = s;
#pragma unroll
        for (int d = 1; d < 32; d <<= 1) {
            int o = __shfl_down_sync(0xFFFFFFFFu, suf, d);
            if (tid + d < 32) suf += o;
        }
        int sufN = __shfl_down_sync(0xFFFFFFFFu, suf, 1);
        if (tid == 31) sufN = 0;
        if (tid == 0) { sh[0] = -1; sh[6] = 0; }
        __syncwarp();
        if (suf >= TOPK && sufN < TOPK) { sh[0] = tid; sh[1] = sufN; }
        __syncwarp();
        if (tid == 0 && sh[0] >= 0) {
            int cum = sh[1];
            int d = sh[0] * 32 + 31;
            for (;; d--) { cum += hist[d]; if (cum >= TOPK) break; }
            sh[3] = d;                // digit of 200th value
            sh[4] = cum - hist[d];    // count with digit > d
            sh[5] = hist[d];
        }
    }
    __syncthreads();

    int ncand;
    bool rare = (sh[0] >= 0) && (sh[4] + sh[5] > CAP);
    if (!rare) {
        // ---- P2 common: collect keys >= digit floor; ONE atomic per warp-iter ----
        uint32_t thrK = (sh[0] < 0) ? (BASE16 << 16)
                                    : ((uint32_t)(BASE16 + (uint32_t)sh[3]) << 16);
        {
            uint4 vcur = (tid < NPRI4) ? gk4[tid] : z4;
#pragma unroll
            for (int it = 0; it < CITER; it++) {
                int inext = tid + (it + 1) * NTB;
                uint4 vnext = (it + 1 < CITER && inext < NPRI4) ? gk4[inext] : z4;
                int base4 = (tid + it * NTB) * 4;

                uint32_t bm0 = __ballot_sync(0xFFFFFFFFu, vcur.x >= thrK);
                uint32_t bm1 = __ballot_sync(0xFFFFFFFFu, vcur.y >= thrK);
                uint32_t bm2 = __ballot_sync(0xFFFFFFFFu, vcur.z >= thrK);
                uint32_t bm3 = __ballot_sync(0xFFFFFFFFu, vcur.w >= thrK);
                int c0 = __popc(bm0), c1 = __popc(bm1), c2 = __popc(bm2);
                int tot = c0 + c1 + c2 + __popc(bm3);
                if (tot) {
                    int base = 0;
                    if (lane == 0) base = atomicAdd(&sh[6], tot);
                    base = __shfl_sync(0xFFFFFFFFu, base, 0);
                    uint32_t below = (1u << lane) - 1u;
                    if (vcur.x >= thrK)
                        spk[base + __popc(bm0 & below)] =
                            ((unsigned long long)vcur.x << 32) | (uint32_t)~(uint32_t)(base4 + 0);
                    if (vcur.y >= thrK)
                        spk[base + c0 + __popc(bm1 & below)] =
                            ((unsigned long long)vcur.y << 32) | (uint32_t)~(uint32_t)(base4 + 1);
                    if (vcur.z >= thrK)
                        spk[base + c0 + c1 + __popc(bm2 & below)] =
                            ((unsigned long long)vcur.z << 32) | (uint32_t)~(uint32_t)(base4 + 2);
                    if (vcur.w >= thrK)
                        spk[base + c0 + c1 + c2 + __popc(bm3 & below)] =
                            ((unsigned long long)vcur.w << 32) | (uint32_t)~(uint32_t)(base4 + 3);
                }
                vcur = vnext;
            }
        }
        __syncthreads();
        ncand = sh[6];
    } else {
        // ---- P2 rare (massive ties at cut digit): exact 32-bit refine ----
        uint32_t top16 = BASE16 + (uint32_t)sh[3];
        int cnt_gt = sh[4];
        if (tid < 256) hist[tid] = 0;
        __syncthreads();
        for (int i = tid; i < NPRI; i += NTB) {
            uint32_t k = gk[i];
            if ((k >> 16) == top16) atomicAdd(&hist[(k >> 8) & 0xFF], 1);
        }
        __syncthreads();
        if (tid == 0) {
            int cum = cnt_gt; int d = 255;
            for (;; d--) { cum += hist[d]; if (cum >= TOPK) break; }
            sh[3] = d; sh[4] = cum - hist[d];
        }
        __syncthreads();
        uint32_t pre24 = (top16 << 8) | (uint32_t)sh[3];
        cnt_gt = sh[4];
        if (tid < 256) hist[tid] = 0;
        __syncthreads();
        for (int i = tid; i < NPRI; i += NTB) {
            uint32_t k = gk[i];
            if ((k >> 8) == pre24) atomicAdd(&hist[k & 0xFF], 1);
        }
        __syncthreads();
        if (tid == 0) {
            int cum = cnt_gt; int d = 255;
            for (;; d--) { cum += hist[d]; if (cum >= TOPK) break; }
            sh[3] = d;
        }
        __syncthreads();
        uint32_t thr = (pre24 << 8) | (uint32_t)sh[3];
        for (int i = tid; i < NPRI; i += NTB) {
            uint32_t k = gk[i];
            if (k > thr) { int p = atomicAdd(&sh[6], 1); spk[p] = ((unsigned long long)k << 32) | (uint32_t)~(uint32_t)i; }
        }
        __syncthreads();
        if (tid == 0) {   // append ties in ascending index order
            int p = sh[6];
            for (int i = 0; i < NPRI && p < TOPK; i++)
                if (gk[i] == thr) { spk[p++] = ((unsigned long long)thr << 32) | (uint32_t)~(uint32_t)i; }
            sh[6] = p;
        }
        __syncthreads();
        ncand = sh[6];
    }

    // ---- P3a: zero output rows + zero-pad spk tail for the sort ----
    for (int i = tid; i < TOPK * 5; i += NTB) orow[i] = 0.0f;
    if (tid < NSORT && tid >= ncand) spk[tid] = 0ull;

    // ---- P3b: 256-wide bitonic sort, descending 64-bit (key desc, idx asc) ----
#pragma unroll
    for (int kk = 2; kk <= NSORT; kk <<= 1) {
        for (int j = kk >> 1; j > 0; j >>= 1) {
            __syncthreads();
            if (tid < NSORT) {
                int ixj = tid ^ j;
                if (ixj > tid) {
                    unsigned long long a = spk[tid], bb = spk[ixj];
                    bool up = (tid & kk) == 0;      // descending
                    if (up ? (a < bb) : (a > bb)) { spk[tid] = bb; spk[ixj] = a; }
                }
            }
        }
    }
    __syncthreads();

    // ---- P3c: place top-200 (sorted position == rank) + gather boxes ----
    int nval = ncand < TOPK ? ncand : TOPK;
    if (tid < nval) {
        unsigned long long e = spk[tid];
        uint32_t kk = (uint32_t)(e >> 32);
        uint32_t idx = ~(uint32_t)e;
        float4 bx = g_boxes[b][idx];
        ssc[tid] = __uint_as_float(kk);
        sbx[tid] = bx;
        sar[tid] = (bx.z - bx.x) * (bx.w - bx.y);
    }
    __syncthreads();

    // ---- P4: IoU suppression masks. Row i split: main thread (tid=i) does the
    //      low half of its word span, helper (tid=200+i, i<184) the high half.
    {
        int i = -1, w0 = 0, w1 = 0;
        if (tid < TOPK) {
            i = tid;
            int wl = i >> 5, span = NW - wl;
            int mine = (i < 184) ? ((span + 1) >> 1) : span;
            w0 = wl; w1 = wl + mine;
        } else if (tid - TOPK < 184) {
            i = tid - TOPK;
            int wl = i >> 5, span = NW - wl;
            w0 = wl + ((span + 1) >> 1); w1 = NW;
        }
        if (i >= 0 && i < nval) {
            if (tid < TOPK)
                for (int w = 0; w < (i >> 5); w++) sup[i * SUPW + w] = 0u;
            float4 A = sbx[i];
            float aa = sar[i];
            for (int w = w0; w < w1; w++) {
                int j0 = w * 32;
                uint32_t m = 0;
#pragma unroll
                for (int jj = 0; jj < 32; jj++) {
                    int j = j0 + jj;
                    float4 B = sbx[j];
                    float xx1 = fmaxf(A.x, B.x);
                    float yy1 = fmaxf(A.y, B.y);
                    float xx2 = fminf(A.z, B.z);
                    float yy2 = fminf(A.w, B.w);
                    float iw = fmaxf(xx2 - xx1, 0.0f);
                    float ih = fmaxf(yy2 - yy1, 0.0f);
                    float inter = iw * ih;
                    float uni = aa + sar[j] - inter;
                    uint32_t bit = 0;
                    if (inter > uni * NMS_HI) bit = 1u << jj;
                    else if (inter > uni * NMS_LO) {
                        if (inter / fmaxf(uni, 1e-12f) > NMS_T) bit = 1u << jj;  // exact ref
                    }
                    m |= bit;
                }
                uint32_t um = (nval >= j0 + 32) ? 0xFFFFFFFFu
                             : ((nval > j0) ? ((1u << (nval - j0)) - 1u) : 0u);
                if (w == (i >> 5))
                    um = (i - j0 < 31) ? (um & (0xFFFFFFFFu << (i - j0 + 1))) : 0u;
                sup[i * SUPW + w] = m & um;
            }
        }
    }
    __syncthreads();

    // ---- P5: warp-parallel NMS sweep (warp 0) + popc compaction bases ----
    if (tid < 32) {
        uint32_t alive_w = 0xFFFFFFFFu;
        int nchunks = (nval + 31) >> 5;
        for (int g = 0; g < nchunks; g++) {
            int rem = nval - g * 32;
            uint32_t vm = (rem >= 32) ? 0xFFFFFFFFu : ((1u << rem) - 1u);
            uint32_t ag = __shfl_sync(0xFFFFFFFFu, alive_w, g) & vm;
            // intra-chunk serial resolve via shuffles (register chain, no LDS)
            uint32_t selfm = (lane < rem) ? sup[(g * 32 + lane) * SUPW + g] : 0u;
#pragma unroll
            for (int bit = 0; bit < 32; bit++) {
                uint32_t sm = __shfl_sync(0xFFFFFFFFu, selfm, bit);
                if ((ag >> bit) & 1u) ag &= ~sm;
            }
            if (lane == g) alive_w = ag;
            // apply chunk g's alive rows to later words (independent LDS, pipelined)
            uint32_t acc = 0;
            int waddr = (lane < NW) ? lane : NW - 1;
#pragma unroll
            for (int bit = 0; bit < 32; bit++) {
                uint32_t s = (bit < rem) ? sup[(g * 32 + bit) * SUPW + waddr] : 0u;
                if ((ag >> bit) & 1u) acc |= s;
            }
            if (lane > g && lane < NW) alive_w &= ~acc;
        }
        uint32_t aw = (lane < NW && lane < nchunks) ? alive_w : 0u;
        if (lane == nchunks - 1) {
            int rem = nval - lane * 32;
            if (rem < 32) aw &= ((1u << (rem > 0 ? rem : 0)) - 1u);
        }
        int pc = __popc(aw);
        int pre = pc;
#pragma unroll
        for (int d = 1; d < 32; d <<= 1) {
            int o = __shfl_up_sync(0xFFFFFFFFu, pre, d);
            if (lane >= d) pre += o;
        }
        if (lane < NW) { salive[lane] = aw; sbase[lane] = pre - pc; }
    }
    __syncthreads();

    // ---- P6: write kept rows compacted to front ----
    for (int i = tid; i < nval; i += NTB) {
        int w = i >> 5, bit = i & 31;
        uint32_t aw = salive[w];
        if ((aw >> bit) & 1u) {
            int q = sbase[w] + __popc(aw & ((1u << bit) - 1u));
            float* r = orow + q * 5;
            float4 bx = sbx[i];
            r[0] = ssc[i];
            r[1] = bx.x;
            r[2] = bx.y;
            r[3] = bx.z;
            r[4] = bx.w;
        }
    }
}

// ---------------------------------------------------------------------------
extern "C" void kernel_launch(void* const* d_in, const int* in_sizes, int n_in,
                              void* d_out, int out_size)
{
    const float* loc    = (const float*)d_in[0];
    const float* conf   = (const float*)d_in[1];
    const float* priors = (const float*)d_in[2];
    float* out = (float*)d_out;

    ssd_decode_softmax<<<(BATCH * NPRI + 255) / 256, 256>>>(loc, conf, priors);
    ssd_select_nms<<<BATCH * NCLS, NTB>>>(out);
}